// round 1
// baseline (speedup 1.0000x reference)
#include <cuda_runtime.h>
#include <math.h>

// Radon transform: img 512x512 f32, angles 180 (int degrees 0..179)
// out[x*180 + a] = sum_y bilinear(img, sy, sx),
//   sx =  cos*(x-c) + sin*(y-c) + c
//   sy = -sin*(x-c) + cos*(y-c) + c,  c = 255.5, zero outside image.

#define NIMG 512
#define NA   180
#define PAD  128
#define PW   768          // padded width/height (512 + 2*128)
#define CEN  255.5f

// Scratch: padded image and padded transposed image (zero border).
__device__ float g_pad [PW * PW];
__device__ float g_padT[PW * PW];

// Build zero-padded image + zero-padded transpose (tiled smem transpose).
__global__ void pad_transpose_kernel(const float* __restrict__ img) {
    __shared__ float tile[32][33];
    const int tx = threadIdx.x;          // 0..31
    const int ty = threadIdx.y;          // 0..7
    const int bx = blockIdx.x * 32;      // col base in padded coords
    const int by = blockIdx.y * 32;      // row base in padded coords

    #pragma unroll
    for (int j = 0; j < 32; j += 8) {
        int r = by + ty + j;
        int q = bx + tx;
        int ir = r - PAD, iq = q - PAD;
        float v = 0.0f;
        if (ir >= 0 && ir < NIMG && iq >= 0 && iq < NIMG)
            v = img[ir * NIMG + iq];
        g_pad[r * PW + q] = v;
        tile[ty + j][tx] = v;
    }
    __syncthreads();
    #pragma unroll
    for (int j = 0; j < 32; j += 8) {
        int r = bx + ty + j;             // transposed coords
        int q = by + tx;
        g_padT[r * PW + q] = tile[tx][ty + j];
    }
}

// Main radon kernel.
// Block: 256 threads = 64 detectors (x) * 4 y-chunks of 128.
// Grid: (512/64, 180) = (8, 180).
__global__ __launch_bounds__(256) void radon_kernel(
    const int* __restrict__ angles, float* __restrict__ out)
{
    __shared__ float s_part[4][64];

    const int tid    = threadIdx.x;
    const int ychunk = tid >> 6;          // 0..3
    const int xl     = tid & 63;          // 0..63
    const int x      = blockIdx.x * 64 + xl;
    const int a      = blockIdx.y;

    // Match reference precision: deg2rad in f32, then high-precision sincos.
    const int adeg = angles[a];
    float tf = (float)adeg * 0.017453292519943295f;
    double td = (double)tf;
    double sd, cd;
    sincos(td, &sd, &cd);
    const float co = (float)cd;
    const float si = (float)sd;

    const float xcn = (float)x - CEN;

    // Padded coords: row R = sy + PAD, col Q = sx + PAD, linear in y.
    float R0 = fmaf(-si, xcn, fmaf(-co, CEN, CEN + (float)PAD));
    float Q0 = fmaf( co, xcn, fmaf(-si, CEN, CEN + (float)PAD));
    float dR = co;
    float dQ = si;
    const float* base = g_pad;

    // Transpose-swap: make the lane direction (over x) mostly contiguous.
    if (fabsf(si) > fabsf(co)) {
        float t0 = R0; R0 = Q0; Q0 = t0;
        float t1 = dR; dR = dQ; dQ = t1;
        base = g_padT;
    }

    const int ybeg = ychunk * 128;
    float yf = (float)ybeg;
    float acc = 0.0f;

    #pragma unroll 4
    for (int i = 0; i < 128; i++) {
        float r = fmaf(yf, dR, R0);
        float q = fmaf(yf, dQ, Q0);
        yf += 1.0f;
        float rf = floorf(r);
        float qf = floorf(q);
        int   ri = (int)rf;
        int   qi = (int)qf;
        float wr = r - rf;
        float wq = q - qf;
        const float* p = base + ri * PW + qi;
        float v00 = __ldg(p);
        float v01 = __ldg(p + 1);
        float v10 = __ldg(p + PW);
        float v11 = __ldg(p + PW + 1);
        float top = fmaf(wq, v01 - v00, v00);
        float bot = fmaf(wq, v11 - v10, v10);
        acc += fmaf(wr, bot - top, top);
    }

    s_part[ychunk][xl] = acc;
    __syncthreads();

    if (tid < 64) {
        float s = s_part[0][tid] + s_part[1][tid]
                + s_part[2][tid] + s_part[3][tid];
        out[(blockIdx.x * 64 + tid) * NA + a] = s;
    }
}

extern "C" void kernel_launch(void* const* d_in, const int* in_sizes, int n_in,
                              void* d_out, int out_size) {
    const float* img    = (const float*)d_in[0];
    const int*   angles = (const int*)d_in[1];
    float*       out    = (float*)d_out;

    dim3 tb(32, 8);
    dim3 tg(PW / 32, PW / 32);
    pad_transpose_kernel<<<tg, tb>>>(img);

    dim3 rg(NIMG / 64, NA);
    radon_kernel<<<rg, 256>>>(angles, out);
}

// round 2
// speedup vs baseline: 1.2190x; 1.2190x over previous
#include <cuda_runtime.h>
#include <math.h>

// Radon transform: img 512x512 f32, angles 180 (int degrees 0..179)
// out[x*180 + a] = sum_y bilinear(img, sy, sx), zero outside image.

#define NIMG 512
#define NA   180
#define PAD  128
#define PW   768
#define CEN  255.5f
#define FXS  20                    // fixed-point fraction bits
#define FXF  1048576.0f            // 2^20

// Scratch: padded scalar images, then (v, v_right) pair tables.
__device__ float  g_pad  [PW * PW];
__device__ float  g_padT [PW * PW];
__device__ float2 g_pair [PW * PW];
__device__ float2 g_pairT[PW * PW];

// Build zero-padded image + zero-padded transpose (tiled smem transpose).
__global__ void pad_transpose_kernel(const float* __restrict__ img) {
    __shared__ float tile[32][33];
    const int tx = threadIdx.x;          // 0..31
    const int ty = threadIdx.y;          // 0..7
    const int bx = blockIdx.x * 32;
    const int by = blockIdx.y * 32;

    #pragma unroll
    for (int j = 0; j < 32; j += 8) {
        int r = by + ty + j;
        int q = bx + tx;
        int ir = r - PAD, iq = q - PAD;
        float v = 0.0f;
        if (ir >= 0 && ir < NIMG && iq >= 0 && iq < NIMG)
            v = img[ir * NIMG + iq];
        g_pad[r * PW + q] = v;
        tile[ty + j][tx] = v;
    }
    __syncthreads();
    #pragma unroll
    for (int j = 0; j < 32; j += 8) {
        int r = bx + ty + j;
        int q = by + tx;
        g_padT[r * PW + q] = tile[tx][ty + j];
    }
}

// Build horizontal pair tables: g_pair[r][q] = (g_pad[r][q], g_pad[r][q+1]).
__global__ __launch_bounds__(256) void pair_kernel() {
    int i = blockIdx.x * 256 + threadIdx.x;     // 0 .. PW*PW-1
    int q = i & (PW - 1);                        // PW=768? not pow2 -> compute
    // PW not a power of two; use div/mod
    int r = i / PW;
    q = i - r * PW;
    bool hasR = (q < PW - 1);
    float a0 = g_pad[i];
    float a1 = hasR ? g_pad[i + 1] : 0.0f;
    g_pair[i] = make_float2(a0, a1);
    float b0 = g_padT[i];
    float b1 = hasR ? g_padT[i + 1] : 0.0f;
    g_pairT[i] = make_float2(b0, b1);
}

// Main radon kernel.
// Block: 128 threads = 4 warps. Warp = 8 detectors x 4 y-phases.
// Grid: (512/32, 180) = (16, 180).
__global__ __launch_bounds__(128) void radon_kernel(
    const int* __restrict__ angles, float* __restrict__ out)
{
    const int lane   = threadIdx.x & 31;
    const int warpId = threadIdx.x >> 5;         // 0..3
    const int d      = lane & 7;                 // detector within warp
    const int yq     = lane >> 3;                // y phase 0..3
    const int x      = blockIdx.x * 32 + warpId * 8 + d;
    const int a      = blockIdx.y;

    // Match reference precision: deg2rad in f32, high-precision sincos.
    const int adeg = angles[a];
    float tf = (float)adeg * 0.017453292519943295f;
    double td = (double)tf;
    double sd, cd;
    sincos(td, &sd, &cd);
    const float co = (float)cd;
    const float si = (float)sd;

    const float xcn = (float)x - CEN;

    // Padded coords at y = yq: R = sy + PAD, Q = sx + PAD.
    float yc0 = (float)yq - CEN;
    float R0 = fmaf(-si, xcn, fmaf(co, yc0, CEN + (float)PAD));
    float Q0 = fmaf( co, xcn, fmaf(si, yc0, CEN + (float)PAD));
    float dR = co;
    float dQ = si;
    const float2* base = g_pair;

    // Transpose-swap: contiguous axis gets the larger per-lane step.
    if (fabsf(si) > fabsf(co)) {
        float t0 = R0; R0 = Q0; Q0 = t0;
        float t1 = dR; dR = dQ; dQ = t1;
        base = g_pairT;
    }

    // Fixed-point s11.20 stepping; per-thread y-stride is 4.
    int Rfx  = __float2int_rn(R0 * FXF);
    int Qfx  = __float2int_rn(Q0 * FXF);
    int dR4  = __float2int_rn(dR * (4.0f * FXF));
    int dQ4  = __float2int_rn(dQ * (4.0f * FXF));

    float acc0 = 0.0f, acc1 = 0.0f;

    #pragma unroll 2
    for (int it = 0; it < 32; ++it) {
        int   idxv[4];
        float wrv[4], wqv[4];
        #pragma unroll
        for (int j = 0; j < 4; ++j) {
            int ri = Rfx >> FXS;
            int qi = Qfx >> FXS;
            idxv[j] = ri * PW + qi;
            // exact fraction via mantissa splice: 1 + frac*2^-20, then -1
            int wrb = 0x3F800000 | ((Rfx & 0xFFFFF) << 3);
            int wqb = 0x3F800000 | ((Qfx & 0xFFFFF) << 3);
            wrv[j] = __int_as_float(wrb) - 1.0f;
            wqv[j] = __int_as_float(wqb) - 1.0f;
            Rfx += dR4;
            Qfx += dQ4;
        }
        float2 t0 = __ldg(base + idxv[0]);
        float2 b0 = __ldg(base + idxv[0] + PW);
        float2 t1 = __ldg(base + idxv[1]);
        float2 b1 = __ldg(base + idxv[1] + PW);
        float2 t2 = __ldg(base + idxv[2]);
        float2 b2 = __ldg(base + idxv[2] + PW);
        float2 t3 = __ldg(base + idxv[3]);
        float2 b3 = __ldg(base + idxv[3] + PW);

        {
            float top = fmaf(wqv[0], t0.y - t0.x, t0.x);
            float bot = fmaf(wqv[0], b0.y - b0.x, b0.x);
            acc0 += fmaf(wrv[0], bot - top, top);
        }
        {
            float top = fmaf(wqv[1], t1.y - t1.x, t1.x);
            float bot = fmaf(wqv[1], b1.y - b1.x, b1.x);
            acc1 += fmaf(wrv[1], bot - top, top);
        }
        {
            float top = fmaf(wqv[2], t2.y - t2.x, t2.x);
            float bot = fmaf(wqv[2], b2.y - b2.x, b2.x);
            acc0 += fmaf(wrv[2], bot - top, top);
        }
        {
            float top = fmaf(wqv[3], t3.y - t3.x, t3.x);
            float bot = fmaf(wqv[3], b3.y - b3.x, b3.x);
            acc1 += fmaf(wrv[3], bot - top, top);
        }
    }

    float acc = acc0 + acc1;
    // Reduce over the 4 y-phases (lanes d, d+8, d+16, d+24).
    acc += __shfl_xor_sync(0xffffffffu, acc, 16);
    acc += __shfl_xor_sync(0xffffffffu, acc, 8);

    if (lane < 8)
        out[x * NA + a] = acc;
}

extern "C" void kernel_launch(void* const* d_in, const int* in_sizes, int n_in,
                              void* d_out, int out_size) {
    const float* img    = (const float*)d_in[0];
    const int*   angles = (const int*)d_in[1];
    float*       out    = (float*)d_out;

    dim3 tb(32, 8);
    dim3 tg(PW / 32, PW / 32);
    pad_transpose_kernel<<<tg, tb>>>(img);

    pair_kernel<<<(PW * PW + 255) / 256, 256>>>();

    dim3 rg(NIMG / 32, NA);
    radon_kernel<<<rg, 128>>>(angles, out);
}

// round 3
// speedup vs baseline: 1.4805x; 1.2146x over previous
#include <cuda_runtime.h>
#include <math.h>

// Radon transform: img 512x512 f32, angles 180 (int degrees 0..179)
// out[x*180 + a] = sum_y bilinear(img, sy, sx), zero outside image.

#define NIMG 512
#define NA   180
#define PAD  128
#define PW   768
#define CEN  255.5f
#define FXS  20                    // fixed-point fraction bits
#define FXF  1048576.0f            // 2^20

// Quad tables: g_quad[r*PW+q] = (v[r][q], v[r][q+1], v[r+1][q], v[r+1][q+1])
// for the zero-padded image (and its transpose).
__device__ float4 g_quad [PW * PW];
__device__ float4 g_quadT[PW * PW];

// Build both quad tables directly from img (zero outside).
__global__ __launch_bounds__(256) void quad_build_kernel(
    const float* __restrict__ img)
{
    int i = blockIdx.x * 256 + threadIdx.x;
    if (i >= PW * PW) return;
    int r = i / PW;
    int q = i - r * PW;
    int ir = r - PAD;               // image row (pad orientation)
    int iq = q - PAD;               // image col

    bool r0 = (ir >= 0) & (ir < NIMG);
    bool r1 = (ir + 1 >= 0) & (ir + 1 < NIMG);
    bool q0 = (iq >= 0) & (iq < NIMG);
    bool q1 = (iq + 1 >= 0) & (iq + 1 < NIMG);

    // Pad orientation: rows = ir, cols = iq.
    {
        float v00 = (r0 & q0) ? __ldg(img + ir * NIMG + iq)           : 0.0f;
        float v01 = (r0 & q1) ? __ldg(img + ir * NIMG + iq + 1)       : 0.0f;
        float v10 = (r1 & q0) ? __ldg(img + (ir + 1) * NIMG + iq)     : 0.0f;
        float v11 = (r1 & q1) ? __ldg(img + (ir + 1) * NIMG + iq + 1) : 0.0f;
        g_quad[i] = make_float4(v00, v01, v10, v11);
    }
    // Transposed orientation: padT[r][q] = img[q'][r'].
    {
        float v00 = (r0 & q0) ? __ldg(img + iq * NIMG + ir)           : 0.0f;
        float v01 = (r0 & q1) ? __ldg(img + (iq + 1) * NIMG + ir)     : 0.0f;
        float v10 = (r1 & q0) ? __ldg(img + iq * NIMG + ir + 1)       : 0.0f;
        float v11 = (r1 & q1) ? __ldg(img + (iq + 1) * NIMG + ir + 1) : 0.0f;
        g_quadT[i] = make_float4(v00, v01, v10, v11);
    }
}

// Main radon kernel.
// Block: 128 threads = 4 warps. Warp = 8 detectors x 4 y-phases.
// Grid: (512/32, 180) = (16, 180).
__global__ __launch_bounds__(128) void radon_kernel(
    const int* __restrict__ angles, float* __restrict__ out)
{
    const int lane   = threadIdx.x & 31;
    const int warpId = threadIdx.x >> 5;         // 0..3
    const int d      = lane & 7;                 // detector within warp
    const int yq     = lane >> 3;                // y phase 0..3
    const int x      = blockIdx.x * 32 + warpId * 8 + d;
    const int a      = blockIdx.y;

    // Match reference precision: deg2rad in f32, high-precision sincos.
    const int adeg = angles[a];
    float tf = (float)adeg * 0.017453292519943295f;
    double td = (double)tf;
    double sd, cd;
    sincos(td, &sd, &cd);
    const float co = (float)cd;
    const float si = (float)sd;

    const float xcn = (float)x - CEN;

    // Padded coords at y = yq: R = sy + PAD, Q = sx + PAD.
    float yc0 = (float)yq - CEN;
    float R0 = fmaf(-si, xcn, fmaf(co, yc0, CEN + (float)PAD));
    float Q0 = fmaf( co, xcn, fmaf(si, yc0, CEN + (float)PAD));
    float dR = co;
    float dQ = si;
    const float4* base = g_quad;

    // Transpose-swap: contiguous axis gets the larger per-lane step.
    if (fabsf(si) > fabsf(co)) {
        float t0 = R0; R0 = Q0; Q0 = t0;
        float t1 = dR; dR = dQ; dQ = t1;
        base = g_quadT;
    }

    // Fixed-point s11.20 stepping; per-thread y-stride is 4.
    int Rfx = __float2int_rn(R0 * FXF);
    int Qfx = __float2int_rn(Q0 * FXF);
    int dR4 = __float2int_rn(dR * (4.0f * FXF));
    int dQ4 = __float2int_rn(dQ * (4.0f * FXF));

    float acc0 = 0.0f, acc1 = 0.0f, acc2 = 0.0f, acc3 = 0.0f;

    #pragma unroll 2
    for (int it = 0; it < 32; ++it) {
        int   idxv[4];
        float wrv[4], wqv[4];
        #pragma unroll
        for (int j = 0; j < 4; ++j) {
            int ri = Rfx >> FXS;
            int qi = Qfx >> FXS;
            idxv[j] = ri * PW + qi;
            // exact fraction via mantissa splice: 1 + frac*2^-20, then -1
            int wrb = 0x3F800000 | ((Rfx & 0xFFFFF) << 3);
            int wqb = 0x3F800000 | ((Qfx & 0xFFFFF) << 3);
            wrv[j] = __int_as_float(wrb) - 1.0f;
            wqv[j] = __int_as_float(wqb) - 1.0f;
            Rfx += dR4;
            Qfx += dQ4;
        }
        float4 v0 = __ldg(base + idxv[0]);
        float4 v1 = __ldg(base + idxv[1]);
        float4 v2 = __ldg(base + idxv[2]);
        float4 v3 = __ldg(base + idxv[3]);

        {
            float top = fmaf(wqv[0], v0.y - v0.x, v0.x);
            float bot = fmaf(wqv[0], v0.w - v0.z, v0.z);
            acc0 += fmaf(wrv[0], bot - top, top);
        }
        {
            float top = fmaf(wqv[1], v1.y - v1.x, v1.x);
            float bot = fmaf(wqv[1], v1.w - v1.z, v1.z);
            acc1 += fmaf(wrv[1], bot - top, top);
        }
        {
            float top = fmaf(wqv[2], v2.y - v2.x, v2.x);
            float bot = fmaf(wqv[2], v2.w - v2.z, v2.z);
            acc2 += fmaf(wrv[2], bot - top, top);
        }
        {
            float top = fmaf(wqv[3], v3.y - v3.x, v3.x);
            float bot = fmaf(wqv[3], v3.w - v3.z, v3.z);
            acc3 += fmaf(wrv[3], bot - top, top);
        }
    }

    float acc = (acc0 + acc1) + (acc2 + acc3);
    // Reduce over the 4 y-phases (lanes d, d+8, d+16, d+24).
    acc += __shfl_xor_sync(0xffffffffu, acc, 16);
    acc += __shfl_xor_sync(0xffffffffu, acc, 8);

    if (lane < 8)
        out[x * NA + a] = acc;
}

extern "C" void kernel_launch(void* const* d_in, const int* in_sizes, int n_in,
                              void* d_out, int out_size) {
    const float* img    = (const float*)d_in[0];
    const int*   angles = (const int*)d_in[1];
    float*       out    = (float*)d_out;

    quad_build_kernel<<<(PW * PW + 255) / 256, 256>>>(img);

    dim3 rg(NIMG / 32, NA);
    radon_kernel<<<rg, 128>>>(angles, out);
}

// round 4
// speedup vs baseline: 1.7944x; 1.2120x over previous
#include <cuda_runtime.h>
#include <math.h>

// Radon transform: img 512x512 f32, angles 180 (int degrees 0..179)
// out[x*180 + a] = sum_y bilinear(img, sy, sx), zero outside image.

#define NIMG 512
#define NA   180
#define PAD  128
#define PW   768
#define CEN  255.5f
#define FXS  20                    // fixed-point fraction bits
#define FXF  1048576.0f            // 2^20
#define NSPLIT 4                   // y-chunks per detector line

// Quad tables: g_quad[r*PW+q] = (v[r][q], v[r][q+1], v[r+1][q], v[r+1][q+1])
__device__ float4 g_quad [PW * PW];
__device__ float4 g_quadT[PW * PW];
__device__ float2 g_trig [NA];                    // (cos, sin) per angle
__device__ float  g_part [NSPLIT * NIMG * NA];    // partial sums per y-chunk

// Build both quad tables directly from img (zero outside) + trig table.
__global__ __launch_bounds__(256) void quad_build_kernel(
    const float* __restrict__ img, const int* __restrict__ angles)
{
    int i = blockIdx.x * 256 + threadIdx.x;

    if (i < NA) {
        // Match reference precision: deg2rad in f32, then hi-prec sincos.
        float tf = (float)angles[i] * 0.017453292519943295f;
        double sd, cd;
        sincos((double)tf, &sd, &cd);
        g_trig[i] = make_float2((float)cd, (float)sd);
    }

    if (i >= PW * PW) return;
    int r = i / PW;
    int q = i - r * PW;
    int ir = r - PAD;
    int iq = q - PAD;

    bool r0 = (ir >= 0) & (ir < NIMG);
    bool r1 = (ir + 1 >= 0) & (ir + 1 < NIMG);
    bool q0 = (iq >= 0) & (iq < NIMG);
    bool q1 = (iq + 1 >= 0) & (iq + 1 < NIMG);

    {
        float v00 = (r0 & q0) ? __ldg(img + ir * NIMG + iq)           : 0.0f;
        float v01 = (r0 & q1) ? __ldg(img + ir * NIMG + iq + 1)       : 0.0f;
        float v10 = (r1 & q0) ? __ldg(img + (ir + 1) * NIMG + iq)     : 0.0f;
        float v11 = (r1 & q1) ? __ldg(img + (ir + 1) * NIMG + iq + 1) : 0.0f;
        g_quad[i] = make_float4(v00, v01, v10, v11);
    }
    {
        float v00 = (r0 & q0) ? __ldg(img + iq * NIMG + ir)           : 0.0f;
        float v01 = (r0 & q1) ? __ldg(img + (iq + 1) * NIMG + ir)     : 0.0f;
        float v10 = (r1 & q0) ? __ldg(img + iq * NIMG + ir + 1)       : 0.0f;
        float v11 = (r1 & q1) ? __ldg(img + (iq + 1) * NIMG + ir + 1) : 0.0f;
        g_quadT[i] = make_float4(v00, v01, v10, v11);
    }
}

// Main radon kernel.
// Block: 128 threads = 4 warps. Warp = 8 detectors x 4 y-phases.
// Grid: (512/32, 180, NSPLIT); each block does a 128-row y-chunk.
__global__ __launch_bounds__(128) void radon_kernel(float* __restrict__ dummy)
{
    const int lane   = threadIdx.x & 31;
    const int warpId = threadIdx.x >> 5;
    const int d      = lane & 7;
    const int yq     = lane >> 3;
    const int x      = blockIdx.x * 32 + warpId * 8 + d;
    const int a      = blockIdx.y;
    const int chunk  = blockIdx.z;

    const float2 cs = g_trig[a];
    const float co = cs.x;
    const float si = cs.y;

    const float xcn = (float)x - CEN;

    // Padded coords at y = chunk*128 + yq.
    float yc0 = (float)(chunk * 128 + yq) - CEN;
    float R0 = fmaf(-si, xcn, fmaf(co, yc0, CEN + (float)PAD));
    float Q0 = fmaf( co, xcn, fmaf(si, yc0, CEN + (float)PAD));
    float dR = co;
    float dQ = si;
    const float4* base = g_quad;

    // Transpose-swap: contiguous axis gets the larger per-lane step.
    if (fabsf(si) > fabsf(co)) {
        float t0 = R0; R0 = Q0; Q0 = t0;
        float t1 = dR; dR = dQ; dQ = t1;
        base = g_quadT;
    }

    // Fixed-point s11.20 stepping; per-thread y-stride is 4.
    int Rfx = __float2int_rn(R0 * FXF);
    int Qfx = __float2int_rn(Q0 * FXF);
    int dR4 = __float2int_rn(dR * (4.0f * FXF));
    int dQ4 = __float2int_rn(dQ * (4.0f * FXF));

    float acc0 = 0.0f, acc1 = 0.0f;

    // 32 samples per thread: 8 batches of 4.
    #pragma unroll 2
    for (int it = 0; it < 8; ++it) {
        int   idxv[4];
        float wrv[4], wqv[4];
        #pragma unroll
        for (int j = 0; j < 4; ++j) {
            int ri = Rfx >> FXS;
            int qi = Qfx >> FXS;
            idxv[j] = ri * PW + qi;
            int wrb = 0x3F800000 | ((Rfx & 0xFFFFF) << 3);
            int wqb = 0x3F800000 | ((Qfx & 0xFFFFF) << 3);
            wrv[j] = __int_as_float(wrb) - 1.0f;
            wqv[j] = __int_as_float(wqb) - 1.0f;
            Rfx += dR4;
            Qfx += dQ4;
        }
        float4 v0 = __ldg(base + idxv[0]);
        float4 v1 = __ldg(base + idxv[1]);
        float4 v2 = __ldg(base + idxv[2]);
        float4 v3 = __ldg(base + idxv[3]);

        {
            float top = fmaf(wqv[0], v0.y - v0.x, v0.x);
            float bot = fmaf(wqv[0], v0.w - v0.z, v0.z);
            acc0 += fmaf(wrv[0], bot - top, top);
        }
        {
            float top = fmaf(wqv[1], v1.y - v1.x, v1.x);
            float bot = fmaf(wqv[1], v1.w - v1.z, v1.z);
            acc1 += fmaf(wrv[1], bot - top, top);
        }
        {
            float top = fmaf(wqv[2], v2.y - v2.x, v2.x);
            float bot = fmaf(wqv[2], v2.w - v2.z, v2.z);
            acc0 += fmaf(wrv[2], bot - top, top);
        }
        {
            float top = fmaf(wqv[3], v3.y - v3.x, v3.x);
            float bot = fmaf(wqv[3], v3.w - v3.z, v3.z);
            acc1 += fmaf(wrv[3], bot - top, top);
        }
    }

    float acc = acc0 + acc1;
    // Reduce over the 4 y-phases (lanes d, d+8, d+16, d+24).
    acc += __shfl_xor_sync(0xffffffffu, acc, 16);
    acc += __shfl_xor_sync(0xffffffffu, acc, 8);

    if (lane < 8)
        g_part[(chunk * NIMG + x) * NA + a] = acc;
}

// Combine the NSPLIT partial sums (deterministic fixed order).
__global__ __launch_bounds__(256) void reduce_kernel(float* __restrict__ out)
{
    int i = blockIdx.x * 256 + threadIdx.x;
    if (i >= NIMG * NA) return;
    float s = g_part[i];
    #pragma unroll
    for (int c = 1; c < NSPLIT; ++c)
        s += g_part[c * NIMG * NA + i];
    out[i] = s;
}

extern "C" void kernel_launch(void* const* d_in, const int* in_sizes, int n_in,
                              void* d_out, int out_size) {
    const float* img    = (const float*)d_in[0];
    const int*   angles = (const int*)d_in[1];
    float*       out    = (float*)d_out;

    quad_build_kernel<<<(PW * PW + 255) / 256, 256>>>(img, angles);

    dim3 rg(NIMG / 32, NA, NSPLIT);
    radon_kernel<<<rg, 128>>>(out);

    reduce_kernel<<<(NIMG * NA + 255) / 256, 256>>>(out);
}

// round 5
// speedup vs baseline: 2.0946x; 1.1673x over previous
#include <cuda_runtime.h>
#include <cuda_fp16.h>
#include <math.h>

// Radon transform: img 512x512 f32, angles 180 (int degrees 0..179)
// out[x*180 + a] = sum_y bilinear(img, sy, sx), zero outside image.

#define NIMG 512
#define NA   180
#define PAD  128
#define PW   768
#define CEN  255.5f
#define FXS  20                    // fixed-point fraction bits
#define FXF  1048576.0f            // 2^20
#define NSPLIT 4                   // y-chunks per detector line

// fp16 quad tables: entry = {half2(v00,v01), half2(v10,v11)} of the 2x2
// bilinear stencil at (r,q) of the zero-padded image / its transpose.
__device__ uint2  g_quadH [PW * PW];
__device__ uint2  g_quadTH[PW * PW];
__device__ float2 g_trig  [NA];                   // (cos, sin) per angle
__device__ float  g_part  [NSPLIT * NIMG * NA];   // partial sums per y-chunk

// Stage A: pad-orientation quad table, row-major coalesced reads. + trig.
__global__ __launch_bounds__(256) void quad_build_kernel(
    const float* __restrict__ img, const int* __restrict__ angles)
{
    int i = blockIdx.x * 256 + threadIdx.x;

    if (i < NA) {
        // Match reference precision: deg2rad in f32, then hi-prec sincos.
        float tf = (float)angles[i] * 0.017453292519943295f;
        double sd, cd;
        sincos((double)tf, &sd, &cd);
        g_trig[i] = make_float2((float)cd, (float)sd);
    }

    if (i >= PW * PW) return;
    int r = i / PW;
    int q = i - r * PW;
    int ir = r - PAD;
    int iq = q - PAD;

    bool r0 = ((unsigned)ir      < NIMG);
    bool r1 = ((unsigned)(ir+1)  < NIMG);
    bool q0 = ((unsigned)iq      < NIMG);
    bool q1 = ((unsigned)(iq+1)  < NIMG);

    float v00 = (r0 & q0) ? __ldg(img + ir * NIMG + iq)           : 0.0f;
    float v01 = (r0 & q1) ? __ldg(img + ir * NIMG + iq + 1)       : 0.0f;
    float v10 = (r1 & q0) ? __ldg(img + (ir + 1) * NIMG + iq)     : 0.0f;
    float v11 = (r1 & q1) ? __ldg(img + (ir + 1) * NIMG + iq + 1) : 0.0f;

    __half2 h01 = __floats2half2_rn(v00, v01);
    __half2 h23 = __floats2half2_rn(v10, v11);
    uint2 u;
    u.x = *reinterpret_cast<unsigned*>(&h01);
    u.y = *reinterpret_cast<unsigned*>(&h23);
    g_quadH[i] = u;
}

// Stage B: transposed table = tiled transpose + in-quad 2x2 swizzle.
// quadT[r][q] = (v00,v10,v01,v11) of quad[q][r].
__global__ __launch_bounds__(256) void quad_transpose_kernel() {
    __shared__ uint2 tile[32][33];
    const int tx = threadIdx.x;          // 0..31
    const int ty = threadIdx.y;          // 0..7
    const int bx = blockIdx.x * 32;
    const int by = blockIdx.y * 32;

    #pragma unroll
    for (int j = 0; j < 32; j += 8)
        tile[ty + j][tx] = g_quadH[(by + ty + j) * PW + (bx + tx)];
    __syncthreads();
    #pragma unroll
    for (int j = 0; j < 32; j += 8) {
        uint2 A = tile[tx][ty + j];
        uint2 B;
        B.x = __byte_perm(A.x, A.y, 0x5410);   // (v00, v10)
        B.y = __byte_perm(A.x, A.y, 0x7632);   // (v01, v11)
        g_quadTH[(bx + ty + j) * PW + (by + tx)] = B;
    }
}

// Main radon kernel.
// Block: 128 threads = 4 warps. Warp = 8 detectors x 4 y-phases.
// Grid: (512/32, 180, NSPLIT); each block does a 128-row y-chunk.
__global__ __launch_bounds__(128) void radon_kernel()
{
    const int lane   = threadIdx.x & 31;
    const int warpId = threadIdx.x >> 5;
    const int d      = lane & 7;
    const int yq     = lane >> 3;
    const int x      = blockIdx.x * 32 + warpId * 8 + d;
    const int a      = blockIdx.y;
    const int chunk  = blockIdx.z;

    const float2 cs = g_trig[a];
    const float co = cs.x;
    const float si = cs.y;

    const float xcn = (float)x - CEN;

    // Padded coords at y = chunk*128 + yq.
    float yc0 = (float)(chunk * 128 + yq) - CEN;
    float R0 = fmaf(-si, xcn, fmaf(co, yc0, CEN + (float)PAD));
    float Q0 = fmaf( co, xcn, fmaf(si, yc0, CEN + (float)PAD));
    float dR = co;
    float dQ = si;
    const uint2* base = g_quadH;

    // Transpose-swap: contiguous axis gets the larger per-lane step.
    if (fabsf(si) > fabsf(co)) {
        float t0 = R0; R0 = Q0; Q0 = t0;
        float t1 = dR; dR = dQ; dQ = t1;
        base = g_quadTH;
    }

    // Fixed-point s11.20 stepping; per-thread y-stride is 4.
    int Rfx = __float2int_rn(R0 * FXF);
    int Qfx = __float2int_rn(Q0 * FXF);
    int dR4 = __float2int_rn(dR * (4.0f * FXF));
    int dQ4 = __float2int_rn(dQ * (4.0f * FXF));

    float acc0 = 0.0f, acc1 = 0.0f;

    // 32 samples per thread: 8 batches of 4.
    #pragma unroll 2
    for (int it = 0; it < 8; ++it) {
        int   idxv[4];
        float wrv[4], wqv[4];
        #pragma unroll
        for (int j = 0; j < 4; ++j) {
            int ri = Rfx >> FXS;
            int qi = Qfx >> FXS;
            idxv[j] = ri * PW + qi;
            int wrb = 0x3F800000 | ((Rfx & 0xFFFFF) << 3);
            int wqb = 0x3F800000 | ((Qfx & 0xFFFFF) << 3);
            wrv[j] = __int_as_float(wrb) - 1.0f;
            wqv[j] = __int_as_float(wqb) - 1.0f;
            Rfx += dR4;
            Qfx += dQ4;
        }
        uint2 u0 = __ldg(base + idxv[0]);
        uint2 u1 = __ldg(base + idxv[1]);
        uint2 u2 = __ldg(base + idxv[2]);
        uint2 u3 = __ldg(base + idxv[3]);

        {
            float2 t = __half22float2(*reinterpret_cast<__half2*>(&u0.x));
            float2 b = __half22float2(*reinterpret_cast<__half2*>(&u0.y));
            float top = fmaf(wqv[0], t.y - t.x, t.x);
            float bot = fmaf(wqv[0], b.y - b.x, b.x);
            acc0 += fmaf(wrv[0], bot - top, top);
        }
        {
            float2 t = __half22float2(*reinterpret_cast<__half2*>(&u1.x));
            float2 b = __half22float2(*reinterpret_cast<__half2*>(&u1.y));
            float top = fmaf(wqv[1], t.y - t.x, t.x);
            float bot = fmaf(wqv[1], b.y - b.x, b.x);
            acc1 += fmaf(wrv[1], bot - top, top);
        }
        {
            float2 t = __half22float2(*reinterpret_cast<__half2*>(&u2.x));
            float2 b = __half22float2(*reinterpret_cast<__half2*>(&u2.y));
            float top = fmaf(wqv[2], t.y - t.x, t.x);
            float bot = fmaf(wqv[2], b.y - b.x, b.x);
            acc0 += fmaf(wrv[2], bot - top, top);
        }
        {
            float2 t = __half22float2(*reinterpret_cast<__half2*>(&u3.x));
            float2 b = __half22float2(*reinterpret_cast<__half2*>(&u3.y));
            float top = fmaf(wqv[3], t.y - t.x, t.x);
            float bot = fmaf(wqv[3], b.y - b.x, b.x);
            acc1 += fmaf(wrv[3], bot - top, top);
        }
    }

    float acc = acc0 + acc1;
    // Reduce over the 4 y-phases (lanes d, d+8, d+16, d+24).
    acc += __shfl_xor_sync(0xffffffffu, acc, 16);
    acc += __shfl_xor_sync(0xffffffffu, acc, 8);

    if (lane < 8)
        g_part[(chunk * NIMG + x) * NA + a] = acc;
}

// Combine the NSPLIT partial sums (deterministic fixed order).
__global__ __launch_bounds__(256) void reduce_kernel(float* __restrict__ out)
{
    int i = blockIdx.x * 256 + threadIdx.x;
    if (i >= NIMG * NA) return;
    float s = g_part[i];
    #pragma unroll
    for (int c = 1; c < NSPLIT; ++c)
        s += g_part[c * NIMG * NA + i];
    out[i] = s;
}

extern "C" void kernel_launch(void* const* d_in, const int* in_sizes, int n_in,
                              void* d_out, int out_size) {
    const float* img    = (const float*)d_in[0];
    const int*   angles = (const int*)d_in[1];
    float*       out    = (float*)d_out;

    quad_build_kernel<<<(PW * PW + 255) / 256, 256>>>(img, angles);

    dim3 tb(32, 8);
    dim3 tg(PW / 32, PW / 32);
    quad_transpose_kernel<<<tg, tb>>>();

    dim3 rg(NIMG / 32, NA, NSPLIT);
    radon_kernel<<<rg, 128>>>();

    reduce_kernel<<<(NIMG * NA + 255) / 256, 256>>>(out);
}